// round 9
// baseline (speedup 1.0000x reference)
#include <cuda_runtime.h>

#define NGRID   41088
#define PMAX    404
#define MDIM    192
#define KR      192
#define BCN     1024
#define TWO_PI_F 6.28318530717958647692f

typedef unsigned long long u64;
typedef unsigned int u32;

// Stage-A output: (re,im) pairs, layout [m][k][bc]
__device__ u64 g_ri[(size_t)MDIM * KR * BCN];
// Stage-B staging: (re,im) pairs, layout [m][l][bc]
__device__ u64 g_st[(size_t)MDIM * MDIM * BCN];

__device__ __forceinline__ u64 ffma2(u64 a, u64 b, u64 c) {
    u64 d; asm("fma.rn.f32x2 %0,%1,%2,%3;" : "=l"(d) : "l"(a), "l"(b), "l"(c)); return d;
}
__device__ __forceinline__ u64 pk2(float lo, float hi) {
    u64 r; asm("mov.b64 %0,{%1,%2};" : "=l"(r) : "f"(lo), "f"(hi)); return r;
}
__device__ __forceinline__ void lds2(u64& a, u64& b, u32 addr) {
    asm volatile("ld.shared.v2.u64 {%0,%1},[%2];" : "=l"(a), "=l"(b) : "r"(addr));
}
__device__ __forceinline__ float4 lds4f(u32 addr) {
    float4 v;
    asm volatile("ld.shared.v4.f32 {%0,%1,%2,%3},[%4];"
                 : "=f"(v.x), "=f"(v.y), "=f"(v.z), "=f"(v.w) : "r"(addr));
    return v;
}
__device__ __forceinline__ void sts1(u32 addr, float a) {
    asm volatile("st.shared.f32 [%0],%1;" :: "r"(addr), "f"(a));
}
__device__ __forceinline__ u32 s2u(const void* p) {
    u32 a; asm("{.reg .u64 t; cvta.to.shared.u64 t,%1; cvt.u32.u64 %0,t;}" : "=r"(a) : "l"(p)); return a;
}
__device__ __forceinline__ void cpa16(u32 dst, const void* src, int bytes) {
    asm volatile("cp.async.cg.shared.global [%0],[%1],16,%2;" :: "r"(dst), "l"(src), "r"(bytes));
}
__device__ __forceinline__ void cpcommit() { asm volatile("cp.async.commit_group;"); }
__device__ __forceinline__ void cpwait0()  { asm volatile("cp.async.wait_group 0;"); }
__device__ __forceinline__ u32 cvt_tf32(float f) {
    u32 r; asm("cvt.rna.tf32.f32 %0,%1;" : "=r"(r) : "f"(f)); return r;
}
__device__ __forceinline__ void split_tf32(float v, u32& h, u32& l) {
    h = cvt_tf32(v);
    l = cvt_tf32(v - __uint_as_float(h));
}
__device__ __forceinline__ void mma_tf32(float* c, const u32* a, u32 b0, u32 b1) {
    asm volatile(
        "mma.sync.aligned.m16n8k8.row.col.f32.tf32.tf32.f32 "
        "{%0,%1,%2,%3},{%4,%5,%6,%7},{%8,%9},{%0,%1,%2,%3};"
        : "+f"(c[0]), "+f"(c[1]), "+f"(c[2]), "+f"(c[3])
        : "r"(a[0]), "r"(a[1]), "r"(a[2]), "r"(a[3]), "r"(b0), "r"(b1));
}

// ---------------------------------------------------------------------------
// Stage A (tensor, no smem): folded per-ring DFT as tf32 MMA (3xtf32 split).
//   re[m,bc] = sum_q c[q,m]*xplus[q,bc],  im[m,bc] = sum_q s[q,m]*xminus[q,bc]
// grid = (16 bc-tiles of 64, 3 m-tiles of 64, 192 rings big-first), 256 thr.
// Warp (mt 0..3, nh 0..1) owns D[16m x 32bc]; all operands loaded straight
// from gmem into the verified m16n8k8 fragment registers. No smem, no syncs.
// ---------------------------------------------------------------------------
extern "C" __global__ void __launch_bounds__(256, 2)
sht_stageA(const float* __restrict__ x,
           const float* __restrict__ cosb,
           const float* __restrict__ sinb)
{
    const int t   = threadIdx.x;
    const int bc0 = blockIdx.x * 64;
    const int m0  = blockIdx.y * 64;
    const int z   = blockIdx.z;
    const int k   = (z & 1) ? (96 + (z >> 1)) : (95 - (z >> 1));  // big rings first

    int nlon, slon, mmax;
    if (k < 96) { nlon = 24 + 4 * k; slon = 2 * k * k + 22 * k; mmax = 12 + 2 * k; }
    else { int q = 192 - k; nlon = 20 + 4 * q; slon = NGRID - (2 * q * q + 22 * q); mmax = 10 + 2 * q; }
    if (mmax > MDIM - 1) mmax = MDIM - 1;
    if (m0 > mmax) return;                  // inactive m-tile: never read downstream
    const int half   = nlon >> 1;
    const int ntiles = (half + 16) >> 4;    // ceil((half+1)/16)

    const int w = t >> 5, lane = t & 31;
    const int mt = w & 3, nh = w >> 2;
    const int g = lane >> 2, tq = lane & 3;
    const int mg = m0 + mt * 16 + g;        // lane's m rows: mg, mg+8

    const float* cb = cosb + (size_t)k * PMAX * MDIM;
    const float* sn = sinb + (size_t)k * PMAX * MDIM;

    // lane's x rows (bc = bc0 + nh*32 + nt*8 + g)
    const float* xr0 = x + (size_t)(bc0 + nh * 32 + 0 * 8 + g) * NGRID + slon;
    const float* xr1 = x + (size_t)(bc0 + nh * 32 + 1 * 8 + g) * NGRID + slon;
    const float* xr2 = x + (size_t)(bc0 + nh * 32 + 2 * 8 + g) * NGRID + slon;
    const float* xr3 = x + (size_t)(bc0 + nh * 32 + 3 * 8 + g) * NGRID + slon;

    float ar[4][4], ai[4][4];
#pragma unroll
    for (int n = 0; n < 4; n++)
#pragma unroll
        for (int i = 0; i < 4; i++) { ar[n][i] = 0.f; ai[n][i] = 0.f; }

    // folded x operand for one q: pl = x+ , mi = x-
    auto fold = [&](const float* xrow, int q, float& pl, float& mi) {
        float xf = 0.f, xb = 0.f;
        bool v  = (q <= half);
        bool vb = (q >= 1) && (q < half);
        if (v)  xf = xrow[q];
        if (vb) xb = xrow[nlon - q];
        bool spec = (q == 0) || (q == half);
        pl = v ? (spec ? xf : xf + xb) : 0.f;
        mi = vb ? (xf - xb) : 0.f;
    };

    for (int qt = 0; qt < ntiles; ++qt) {
        int q0 = qt * 16;
#pragma unroll
        for (int ks = 0; ks < 2; ++ks) {
            int qa = q0 + ks * 8 + tq;      // lane's q rows: qa, qa+4 (< 404 always)
            const float* cq0 = cb + (size_t)qa * MDIM;
            const float* cq4 = cq0 + 4 * MDIM;
            const float* sq0 = sn + (size_t)qa * MDIM;
            const float* sq4 = sq0 + 4 * MDIM;

            u32 ach[4], acl[4], ash[4], asl[4];
            split_tf32(cq0[mg],     ach[0], acl[0]);
            split_tf32(cq0[mg + 8], ach[1], acl[1]);
            split_tf32(cq4[mg],     ach[2], acl[2]);
            split_tf32(cq4[mg + 8], ach[3], acl[3]);
            split_tf32(sq0[mg],     ash[0], asl[0]);
            split_tf32(sq0[mg + 8], ash[1], asl[1]);
            split_tf32(sq4[mg],     ash[2], asl[2]);
            split_tf32(sq4[mg + 8], ash[3], asl[3]);

            const float* xrs[4] = {xr0, xr1, xr2, xr3};
#pragma unroll
            for (int nt = 0; nt < 4; ++nt) {
                float pl0, mi0, pl1, mi1;
                fold(xrs[nt], qa,     pl0, mi0);
                fold(xrs[nt], qa + 4, pl1, mi1);
                u32 ph0, plo0, mh0, mlo0, ph1, plo1, mh1, mlo1;
                split_tf32(pl0, ph0, plo0);
                split_tf32(mi0, mh0, mlo0);
                split_tf32(pl1, ph1, plo1);
                split_tf32(mi1, mh1, mlo1);
                mma_tf32(ar[nt], ach, ph0, ph1);    // Ah*Bh
                mma_tf32(ar[nt], ach, plo0, plo1);  // Ah*Bl
                mma_tf32(ar[nt], acl, ph0, ph1);    // Al*Bh
                mma_tf32(ai[nt], ash, mh0, mh1);
                mma_tf32(ai[nt], ash, mlo0, mlo1);
                mma_tf32(ai[nt], asl, mh0, mh1);
            }
        }
    }

    // epilogue: scale by 2*pi, pack (re,im), STG.128 (same mapping as verified)
#pragma unroll
    for (int nt = 0; nt < 4; ++nt) {
        int bc = bc0 + nh * 32 + nt * 8 + tq * 2;
        size_t blo = ((size_t)(m0 + mt * 16 + g) * KR + k) * BCN + bc;
        size_t bhi = ((size_t)(m0 + mt * 16 + g + 8) * KR + k) * BCN + bc;
        ulonglong2 v;
        v.x = pk2(ar[nt][0] * TWO_PI_F, ai[nt][0] * TWO_PI_F);
        v.y = pk2(ar[nt][1] * TWO_PI_F, ai[nt][1] * TWO_PI_F);
        *(ulonglong2*)(g_ri + blo) = v;
        v.x = pk2(ar[nt][2] * TWO_PI_F, ai[nt][2] * TWO_PI_F);
        v.y = pk2(ar[nt][3] * TWO_PI_F, ai[nt][3] * TWO_PI_F);
        *(ulonglong2*)(g_ri + bhi) = v;
    }
}

// ---------------------------------------------------------------------------
// Stage B: per-m GEMM over active latitude band (known-good)
//   st[m,l,bc] = sum_{k in [klo,khi]} A[m,k,bc] * W[m,l,k]
// grid = (16 bc-tiles of 64, 3 l-tiles of 64, 192 m), block = 128.
// ---------------------------------------------------------------------------
extern "C" __global__ void __launch_bounds__(128, 4)
sht_stageB(const float* __restrict__ weight)
{
    __shared__ __align__(16) unsigned char sm[2 * 16 * 512 + 2 * 16 * 272];
    const int t   = threadIdx.x;
    const int bc0 = blockIdx.x * 64;
    const int l0  = blockIdx.y * 64;
    const int m   = blockIdx.z;
    if (l0 + 63 < m) return;                // zero triangle: handled by transpose

    const int tb = t & 15, tl = t >> 4;     // 4 bc, 8 l per thread

    const int klo = (m <= 12) ? 0 : ((m - 11) >> 1);
    int khi = (394 - m) >> 1; if (khi > KR - 1) khi = KR - 1;
    const int kb0 = klo & ~15;
    const int nkt = ((khi - kb0) >> 4) + 1;

    const u32 sb = s2u(sm);
    const u32 AS = sb;                      // buf stride 8192, row 512 B
    const u32 WS = sb + 16384;              // buf stride 4352, row 272 B

    const int lr = t >> 1, kq = (t & 1) * 8;      // W staging: 2 float4 each

    const float* wrow  = weight + ((size_t)m * MDIM + l0 + lr) * KR;
    const u64*   abase = g_ri + ((size_t)m * KR) * BCN + bc0;

    u64 acc[8][4];
#pragma unroll
    for (int j = 0; j < 8; j++)
#pragma unroll
        for (int i = 0; i < 4; i++) acc[j][i] = 0ull;

    float4 w40, w41;
    auto cpa_tile = [&](int buf, int kb) {
#pragma unroll
        for (int c = 0; c < 4; c++) {
            int chunk = t * 4 + c;          // 0..511
            int kk = chunk >> 5, col = chunk & 31;
            int kg = kb + kk;
            int kgc = kg > KR - 1 ? KR - 1 : kg;
            const u64* src = abase + (size_t)kgc * BCN + col * 2;
            int bytes = (kg >= klo && kg <= khi) ? 16 : 0;   // zero-fill outside band
            cpa16(AS + buf * 8192 + kk * 512 + col * 16, src, bytes);
        }
        cpcommit();
    };
    auto ldW = [&](int kb) {
        w40 = *(const float4*)(wrow + kb + kq);
        w41 = *(const float4*)(wrow + kb + kq + 4);
    };
    auto stW = [&](int buf) {
        u32 ws = WS + buf * 4352 + kq * 272 + lr * 4;
        sts1(ws,           w40.x); sts1(ws + 272,     w40.y);
        sts1(ws + 2 * 272, w40.z); sts1(ws + 3 * 272, w40.w);
        sts1(ws + 4 * 272, w41.x); sts1(ws + 5 * 272, w41.y);
        sts1(ws + 6 * 272, w41.z); sts1(ws + 7 * 272, w41.w);
    };
    auto compute = [&](int buf) {
        u32 as_ = AS + buf * 8192 + tb * 16;
        u32 ws  = WS + buf * 4352 + tl * 32;
#pragma unroll
        for (int kk = 0; kk < 16; ++kk) {
            u64 a[4];
            lds2(a[0], a[1], as_ + kk * 512);
            lds2(a[2], a[3], as_ + kk * 512 + 256);
            float4 f0 = lds4f(ws + kk * 272);
            float4 f1 = lds4f(ws + kk * 272 + 16);
            const float fwv[8] = {f0.x, f0.y, f0.z, f0.w, f1.x, f1.y, f1.z, f1.w};
#pragma unroll
            for (int j = 0; j < 8; j++) {
                u64 ww = pk2(fwv[j], fwv[j]);
#pragma unroll
                for (int i = 0; i < 4; i++)
                    acc[j][i] = ffma2(a[i], ww, acc[j][i]);
            }
        }
    };

    cpa_tile(0, kb0);
    ldW(kb0);
    stW(0);
    cpwait0();
    __syncthreads();
    for (int ti = 0; ti < nkt; ++ti) {
        int kb = kb0 + ((ti + 1) << 4);
        bool nx = (ti + 1) < nkt;
        if (nx) { cpa_tile((ti + 1) & 1, kb); ldW(kb); }
        compute(ti & 1);
        if (nx) { stW((ti + 1) & 1); cpwait0(); }
        __syncthreads();
    }

    // coalesced staging writes: [m][l][bc]; thread bc = 2tb,2tb+1, +32
#pragma unroll
    for (int j = 0; j < 8; j++) {
        u64* o = g_st + (((size_t)m * MDIM) + l0 + tl * 8 + j) * BCN + bc0 + tb * 2;
        ulonglong2 w0, w1;
        w0.x = acc[j][0]; w0.y = acc[j][1];
        w1.x = acc[j][2]; w1.y = acc[j][3];
        *(ulonglong2*)o        = w0;
        *(ulonglong2*)(o + 32) = w1;
    }
}

// ---------------------------------------------------------------------------
// Transpose: out[bc][l][m] <- g_st[m][l][bc]; zero for l < m.
// grid = (16 bc-tiles of 64, 6 m-tiles of 32, 192 l), block = 256.
// ---------------------------------------------------------------------------
extern "C" __global__ void __launch_bounds__(256)
sht_transpose(u64* __restrict__ out)
{
    __shared__ u64 smt[32][65];
    const int t   = threadIdx.x;
    const int bc0 = blockIdx.x * 64;
    const int m0  = blockIdx.y * 32;
    const int l   = blockIdx.z;

    const int mr  = t >> 5;            // 0..7
    const int bcc = (t & 31) * 2;      // 0..62
#pragma unroll
    for (int r = 0; r < 4; ++r) {
        int ml = mr + r * 8;
        ulonglong2 v;
        if (l >= m0 + ml)
            v = *(const ulonglong2*)(g_st + (((size_t)(m0 + ml)) * MDIM + l) * BCN + bc0 + bcc);
        else
            v = make_ulonglong2(0ull, 0ull);
        smt[ml][bcc]     = v.x;
        smt[ml][bcc + 1] = v.y;
    }
    __syncthreads();

    const int bcr = t >> 4;            // 0..15
    const int mc  = (t & 15) * 2;      // 0..30
#pragma unroll
    for (int r = 0; r < 4; ++r) {
        int bcl = bcr + r * 16;
        ulonglong2 v;
        v.x = smt[mc][bcl];
        v.y = smt[mc + 1][bcl];
        *(ulonglong2*)(out + (((size_t)(bc0 + bcl)) * MDIM + l) * MDIM + m0 + mc) = v;
    }
}

// ---------------------------------------------------------------------------

extern "C" void kernel_launch(void* const* d_in, const int* in_sizes, int n_in,
                              void* d_out, int out_size)
{
    (void)in_sizes; (void)n_in; (void)out_size;
    const float* x      = (const float*)d_in[0];
    const float* weight = (const float*)d_in[1];
    const float* cosb   = (const float*)d_in[2];
    const float* sinb   = (const float*)d_in[3];

    // (bc-tile, m-tile, ring): all 48 blocks of one ring are bid-adjacent
    dim3 gA(16, 3, 192);
    sht_stageA<<<gA, 256>>>(x, cosb, sinb);

    dim3 gB(16, 3, 192);
    sht_stageB<<<gB, 128>>>(weight);

    dim3 gT(16, 6, 192);
    sht_transpose<<<gT, 256>>>((u64*)d_out);
}

// round 10
// speedup vs baseline: 1.4162x; 1.4162x over previous
#include <cuda_runtime.h>

#define NGRID   41088
#define PMAX    404
#define MDIM    192
#define KR      192
#define KF      96
#define BCN     1024
#define TWO_PI_F 6.28318530717958647692f

typedef unsigned long long u64;
typedef unsigned int u32;

// Pre-folded stage-A output: (re,im) pairs, layout [m][kf][bc], kf in [0,96)
__device__ u64 g_rip[(size_t)MDIM * KF * BCN];   // A+ = A[k] + A[191-k]
__device__ u64 g_rim[(size_t)MDIM * KF * BCN];   // A- = A[k] - A[191-k]
// Stage-B staging: (re,im) pairs, layout [m][l][bc]
__device__ u64 g_st[(size_t)MDIM * MDIM * BCN];

__device__ __forceinline__ u64 ffma2(u64 a, u64 b, u64 c) {
    u64 d; asm("fma.rn.f32x2 %0,%1,%2,%3;" : "=l"(d) : "l"(a), "l"(b), "l"(c)); return d;
}
__device__ __forceinline__ u64 fmul2(u64 a, u64 b) {
    u64 d; asm("mul.rn.f32x2 %0,%1,%2;" : "=l"(d) : "l"(a), "l"(b)); return d;
}
__device__ __forceinline__ u64 fadd2(u64 a, u64 b) {
    u64 d; asm("add.rn.f32x2 %0,%1,%2;" : "=l"(d) : "l"(a), "l"(b)); return d;
}
__device__ __forceinline__ u64 pk2(float lo, float hi) {
    u64 r; asm("mov.b64 %0,{%1,%2};" : "=l"(r) : "f"(lo), "f"(hi)); return r;
}
__device__ __forceinline__ void lds2(u64& a, u64& b, u32 addr) {
    asm volatile("ld.shared.v2.u64 {%0,%1},[%2];" : "=l"(a), "=l"(b) : "r"(addr));
}
__device__ __forceinline__ float4 lds4f(u32 addr) {
    float4 v;
    asm volatile("ld.shared.v4.f32 {%0,%1,%2,%3},[%4];"
                 : "=f"(v.x), "=f"(v.y), "=f"(v.z), "=f"(v.w) : "r"(addr));
    return v;
}
__device__ __forceinline__ void sts4(u32 addr, float a, float b, float c, float d) {
    asm volatile("st.shared.v4.f32 [%0],{%1,%2,%3,%4};" :: "r"(addr), "f"(a), "f"(b), "f"(c), "f"(d));
}
__device__ __forceinline__ void sts2(u32 addr, float a, float b) {
    asm volatile("st.shared.v2.f32 [%0],{%1,%2};" :: "r"(addr), "f"(a), "f"(b));
}
__device__ __forceinline__ void sts1(u32 addr, float a) {
    asm volatile("st.shared.f32 [%0],%1;" :: "r"(addr), "f"(a));
}
__device__ __forceinline__ u32 s2u(const void* p) {
    u32 a; asm("{.reg .u64 t; cvta.to.shared.u64 t,%1; cvt.u32.u64 %0,t;}" : "=r"(a) : "l"(p)); return a;
}
__device__ __forceinline__ void cpa16(u32 dst, const void* src, int bytes) {
    asm volatile("cp.async.cg.shared.global [%0],[%1],16,%2;" :: "r"(dst), "l"(src), "r"(bytes));
}
__device__ __forceinline__ void cpcommit() { asm volatile("cp.async.commit_group;"); }
__device__ __forceinline__ void cpwait0()  { asm volatile("cp.async.wait_group 0;"); }

// ---------------------------------------------------------------------------
// Stage A: folded per-ring DFT on ring PAIRS (k1, 191-k1).
// LONS is pole-symmetric: nlon, basis identical for both rings of a pair.
//   re[m,bc] = sum_{q=0..nlon/2} c[q,m]*xplus[bc,q]   (per ring)
// Epilogue emits pre-folded A+ = A(k1)+A(k2), A- = A(k1)-A(k2), scaled 2*pi.
// grid = (16 bc-tiles of 64, 96 pairs big-first, 3 m-tiles of 64), 256 thr.
// Thread tile: 4 m-pairs x (4 bc ring0 + 4 bc ring1) = 32 FFMA2 / p-step.
// ---------------------------------------------------------------------------
extern "C" __global__ void __launch_bounds__(256, 2)
sht_stageA(const float* __restrict__ x,
           const float* __restrict__ cosb,
           const float* __restrict__ sinb)
{
    __shared__ __align__(16) unsigned char sm[2 * 16 * 512 + 2 * 16 * 1024]; // 49152
    const int t   = threadIdx.x;
    const int bc0 = blockIdx.x * 64;
    const int k1  = 95 - blockIdx.y;        // big rings first (k1=95: nlon 404)
    const int m0  = blockIdx.z * 64;

    const int nlon  = 24 + 4 * k1;
    const int slon1 = 2 * k1 * k1 + 22 * k1;
    const int q2    = k1 + 1;               // = 192 - k2, k2 = 96 + blockIdx.y
    const int slon2 = NGRID - (2 * q2 * q2 + 22 * q2);
    int mmax = 12 + 2 * k1;
    if (mmax > MDIM - 1) mmax = MDIM - 1;   // identical for both rings of pair
    if (m0 > mmax) return;                  // inactive m-tile: never read downstream
    const int half   = nlon >> 1;
    const int ntiles = (half + 16) >> 4;    // ceil((half+1)/16)

    const u32 sb = s2u(sm);
    const u32 CS = sb;                      // [buf][16q][64 m u64], row 512 B
    const u32 XS = sb + 16384;              // [buf][16q][2 ring][64 bc u64], row 1024 B

    // staging roles
    const int ppb = t >> 4, mq = (t & 15) * 4;   // basis: 1 q-row, 4 m
    const int bcr = t >> 1, pq = (t & 1) * 8;    // x: 1 (ring,bc)-row, 8 q
    const int ring = bcr >> 6, bcl = bcr & 63;

    // compute roles
    const int tm = t >> 4, tb = t & 15;          // 4 m-pairs, 4 bc per ring

    const float* xrow  = x + (size_t)(bc0 + bcl) * NGRID + (ring ? slon2 : slon1);
    const float* cbase = cosb + ((size_t)k1 * PMAX) * MDIM + m0 + mq;
    const float* sbase = sinb + ((size_t)k1 * PMAX) * MDIM + m0 + mq;

    u64 acc0[4][4], acc1[4][4];
#pragma unroll
    for (int j = 0; j < 4; j++)
#pragma unroll
        for (int i = 0; i < 4; i++) { acc0[j][i] = 0ull; acc1[j][i] = 0ull; }

    float4 c4, s4, fw0, fw1, bw0, bw1;
    float ps0, ps1;
    int p0s;
    const float4 z4 = make_float4(0.f, 0.f, 0.f, 0.f);

    auto prefetch = [&](int p0) {
        p0s = p0;
        int p = p0 + ppb;                   // p <= 207 < PMAX: in-bounds
        c4 = *(const float4*)(cbase + (size_t)p * MDIM);
        s4 = *(const float4*)(sbase + (size_t)p * MDIM);
        int q0 = p0 + pq;
        if (q0 <= half) {
            fw0 = *(const float4*)(xrow + q0);
            bw0 = *(const float4*)(xrow + nlon - q0 - 4);
            ps0 = (q0 >= 1) ? xrow[nlon - q0] : 0.f;
        } else { fw0 = z4; bw0 = z4; ps0 = 0.f; }
        int q1 = q0 + 4;
        if (q1 <= half) {
            fw1 = *(const float4*)(xrow + q1);
            bw1 = *(const float4*)(xrow + nlon - q1 - 4);
            ps1 = xrow[nlon - q1];
        } else { fw1 = z4; bw1 = z4; ps1 = 0.f; }
    };

    auto fold_emit = [&](u32 a, float4 f, float4 b, float ps, int qv) {
        float fr[4] = {f.x, f.y, f.z, f.w};
        float pr[4] = {ps, b.w, b.z, b.y};
#pragma unroll
        for (int i = 0; i < 4; i++) {
            int q = qv + i;
            bool valid = q <= half;
            bool spec  = (q == 0) || (q == half);
            float pl = valid ? (spec ? fr[i] : fr[i] + pr[i]) : 0.f;
            float mi = (valid && !spec) ? fr[i] - pr[i] : 0.f;
            sts2(a + i * 1024, pl, mi);
        }
    };

    auto store_tile = [&](int buf) {
        u32 cs = CS + buf * 8192 + ppb * 512 + mq * 8;
        sts4(cs,      c4.x, s4.x, c4.y, s4.y);
        sts4(cs + 16, c4.z, s4.z, c4.w, s4.w);
        u32 xa = XS + buf * 16384 + pq * 1024 + ring * 512 + bcl * 8;
        int q0 = p0s + pq;
        fold_emit(xa,        fw0, bw0, ps0, q0);
        fold_emit(xa + 4096, fw1, bw1, ps1, q0 + 4);
    };

    auto compute = [&](int buf) {
        u32 cs = CS + buf * 8192 + tm * 32;
        u32 xs = XS + buf * 16384 + tb * 32;
#pragma unroll
        for (int pp = 0; pp < 16; ++pp) {
            u64 b0, b1, b2, b3;
            lds2(b0, b1, cs + pp * 512);
            lds2(b2, b3, cs + pp * 512 + 16);
            u64 v[4], u[4];
            lds2(v[0], v[1], xs + pp * 1024);
            lds2(v[2], v[3], xs + pp * 1024 + 16);
            lds2(u[0], u[1], xs + pp * 1024 + 512);
            lds2(u[2], u[3], xs + pp * 1024 + 528);
#pragma unroll
            for (int i = 0; i < 4; i++) {
                acc0[0][i] = ffma2(b0, v[i], acc0[0][i]);
                acc0[1][i] = ffma2(b1, v[i], acc0[1][i]);
                acc0[2][i] = ffma2(b2, v[i], acc0[2][i]);
                acc0[3][i] = ffma2(b3, v[i], acc0[3][i]);
                acc1[0][i] = ffma2(b0, u[i], acc1[0][i]);
                acc1[1][i] = ffma2(b1, u[i], acc1[1][i]);
                acc1[2][i] = ffma2(b2, u[i], acc1[2][i]);
                acc1[3][i] = ffma2(b3, u[i], acc1[3][i]);
            }
        }
    };

    prefetch(0);
    store_tile(0);
    __syncthreads();
    for (int ti = 0; ti < ntiles; ++ti) {
        bool nx = (ti + 1) < ntiles;
        if (nx) prefetch((ti + 1) << 4);
        compute(ti & 1);
        if (nx) store_tile((ti + 1) & 1);
        __syncthreads();
    }

    // epilogue: fold across hemisphere pair, scale by 2*pi, STG.128
    const u64 tp2  = pk2(TWO_PI_F, TWO_PI_F);
    const u64 NEG1 = pk2(-1.f, -1.f);
#pragma unroll
    for (int j = 0; j < 4; j++) {
        size_t base = ((size_t)(m0 + tm * 4 + j) * KF + k1) * BCN + bc0 + tb * 4;
        u64* op = g_rip + base;
        u64* om = g_rim + base;
        ulonglong2 wp0, wp1, wm0, wm1;
        wp0.x = fmul2(fadd2(acc0[j][0], acc1[j][0]), tp2);
        wp0.y = fmul2(fadd2(acc0[j][1], acc1[j][1]), tp2);
        wp1.x = fmul2(fadd2(acc0[j][2], acc1[j][2]), tp2);
        wp1.y = fmul2(fadd2(acc0[j][3], acc1[j][3]), tp2);
        wm0.x = fmul2(ffma2(acc1[j][0], NEG1, acc0[j][0]), tp2);
        wm0.y = fmul2(ffma2(acc1[j][1], NEG1, acc0[j][1]), tp2);
        wm1.x = fmul2(ffma2(acc1[j][2], NEG1, acc0[j][2]), tp2);
        wm1.y = fmul2(ffma2(acc1[j][3], NEG1, acc0[j][3]), tp2);
        *(ulonglong2*)op       = wp0;
        *(ulonglong2*)(op + 2) = wp1;
        *(ulonglong2*)om       = wm0;
        *(ulonglong2*)(om + 2) = wm1;
    }
}

// ---------------------------------------------------------------------------
// Stage B: per-m GEMM on pre-folded operands, parity-coherent warps.
//   weight[m,l,k] = (-1)^(l+m) weight[m,l,191-k]
//   st[m,l,bc] = sum_{k in [klo,95]} W[m,l,k] * ( (l+m) even ? A+[k] : A-[k] )
// grid = (16 bc-tiles of 64, 3 l-tiles of 64, 192 m), block = 128.
// A+/A- tiles staged via cp.async (zero-fill below klo); W parity-compacted.
// Warp: parity pw = w&1 (single A tile), bc-half h = w>>1; thread 8 lc x 4 bc.
// ---------------------------------------------------------------------------
extern "C" __global__ void __launch_bounds__(128, 4)
sht_stageB(const float* __restrict__ weight)
{
    __shared__ __align__(16) unsigned char sm[4 * 16 * 512 + 2 * 16 * 256];  // 40960
    const int t   = threadIdx.x;
    const int bc0 = blockIdx.x * 64;
    const int l0  = blockIdx.y * 64;
    const int m   = blockIdx.z;
    if (l0 + 63 < m) return;                // zero triangle: handled by transpose

    const int klo = (m <= 12) ? 0 : ((m - 11) >> 1);   // klo <= 90 < 96
    const int kb0 = klo & ~15;
    const int nkt = ((95 - kb0) >> 4) + 1;  // tiles cover [kb0, 95] exactly

    const u32 sb  = s2u(sm);
    const u32 APS = sb;                     // A+ : [buf][16k][64bc u64], row 512 B
    const u32 AMS = sb + 16384;             // A-
    const u32 WS  = sb + 32768;             // W  : [buf][16k][2 par][32 lc] f32, row 256 B

    // staging roles
    const int lr = t >> 1, kq = (t & 1) * 8;       // W: 1 l-row, 8 k
    const int wpar = (lr + m) & 1, wlc = lr >> 1;

    // compute roles
    const int w = t >> 5, lane = t & 31;
    const int pw  = w & 1;                  // warp parity: 0 -> A+, 1 -> A-
    const int h   = w >> 1;                 // bc half
    const int lc0 = (lane >> 3) * 8;        // 8 consecutive compacted l
    const int bto = h * 32 + (lane & 7) * 4;
    const int dlt = pw ^ (m & 1);           // actual l = l0 + 2*lc + dlt

    const float* wrow   = weight + ((size_t)m * MDIM + l0 + lr) * KR;
    const u64*   apbase = g_rip + ((size_t)m * KF) * BCN + bc0;
    const u64*   ambase = g_rim + ((size_t)m * KF) * BCN + bc0;

    u64 acc[8][4];
#pragma unroll
    for (int j = 0; j < 8; j++)
#pragma unroll
        for (int i = 0; i < 4; i++) acc[j][i] = 0ull;

    float4 w40, w41;
    auto cpa_tile = [&](int buf, int kb) {
#pragma unroll
        for (int c = 0; c < 4; c++) {
            int chunk = t * 4 + c;          // 0..511
            int kk = chunk >> 5, col = chunk & 31;
            int kg = kb + kk;               // kg <= 95 always
            int bytes = (kg >= klo) ? 16 : 0;   // zero-fill below band
            cpa16(APS + buf * 8192 + kk * 512 + col * 16,
                  apbase + (size_t)kg * BCN + col * 2, bytes);
            cpa16(AMS + buf * 8192 + kk * 512 + col * 16,
                  ambase + (size_t)kg * BCN + col * 2, bytes);
        }
        cpcommit();
    };
    auto ldW = [&](int kb) {
        w40 = *(const float4*)(wrow + kb + kq);
        w41 = *(const float4*)(wrow + kb + kq + 4);
    };
    auto stW = [&](int buf) {
        u32 ws = WS + buf * 4096 + wpar * 128 + wlc * 4;
        sts1(ws + (kq + 0) * 256, w40.x);
        sts1(ws + (kq + 1) * 256, w40.y);
        sts1(ws + (kq + 2) * 256, w40.z);
        sts1(ws + (kq + 3) * 256, w40.w);
        sts1(ws + (kq + 4) * 256, w41.x);
        sts1(ws + (kq + 5) * 256, w41.y);
        sts1(ws + (kq + 6) * 256, w41.z);
        sts1(ws + (kq + 7) * 256, w41.w);
    };

    const u32 AT = pw ? AMS : APS;

    auto compute = [&](int buf) {
        u32 as_ = AT + buf * 8192 + bto * 8;
        u32 ws  = WS + buf * 4096 + pw * 128 + lc0 * 4;
#pragma unroll
        for (int kk = 0; kk < 16; ++kk) {
            u64 a[4];
            lds2(a[0], a[1], as_ + kk * 512);
            lds2(a[2], a[3], as_ + kk * 512 + 16);
            float4 f0 = lds4f(ws + kk * 256);
            float4 f1 = lds4f(ws + kk * 256 + 16);
            const float fw[8] = {f0.x, f0.y, f0.z, f0.w, f1.x, f1.y, f1.z, f1.w};
#pragma unroll
            for (int j = 0; j < 8; j++) {
                u64 ww = pk2(fw[j], fw[j]);
#pragma unroll
                for (int i = 0; i < 4; i++)
                    acc[j][i] = ffma2(a[i], ww, acc[j][i]);
            }
        }
    };

    cpa_tile(0, kb0);
    ldW(kb0);
    stW(0);
    cpwait0();
    __syncthreads();
    for (int ti = 0; ti < nkt; ++ti) {
        int kb = kb0 + ((ti + 1) << 4);
        bool nx = (ti + 1) < nkt;
        if (nx) { cpa_tile((ti + 1) & 1, kb); ldW(kb); }
        compute(ti & 1);
        if (nx) { stW((ti + 1) & 1); cpwait0(); }
        __syncthreads();
    }

    // coalesced staging writes: [m][l][bc]; rows l = l0 + 2*(lc0+j) + dlt
#pragma unroll
    for (int j = 0; j < 8; j++) {
        int l = l0 + 2 * (lc0 + j) + dlt;
        u64* o = g_st + (((size_t)m * MDIM) + l) * BCN + bc0 + bto;
        ulonglong2 w0, w1;
        w0.x = acc[j][0]; w0.y = acc[j][1];
        w1.x = acc[j][2]; w1.y = acc[j][3];
        *(ulonglong2*)o       = w0;
        *(ulonglong2*)(o + 2) = w1;
    }
}

// ---------------------------------------------------------------------------
// Transpose: out[bc][l][m] <- g_st[m][l][bc]; zero for l < m.
// grid = (16 bc-tiles of 64, 6 m-tiles of 32, 192 l), block = 256.
// ---------------------------------------------------------------------------
extern "C" __global__ void __launch_bounds__(256)
sht_transpose(u64* __restrict__ out)
{
    __shared__ u64 smt[32][65];
    const int t   = threadIdx.x;
    const int bc0 = blockIdx.x * 64;
    const int m0  = blockIdx.y * 32;
    const int l   = blockIdx.z;

    const int mr  = t >> 5;            // 0..7
    const int bcc = (t & 31) * 2;      // 0..62
#pragma unroll
    for (int r = 0; r < 4; ++r) {
        int ml = mr + r * 8;
        ulonglong2 v;
        if (l >= m0 + ml)
            v = *(const ulonglong2*)(g_st + (((size_t)(m0 + ml)) * MDIM + l) * BCN + bc0 + bcc);
        else
            v = make_ulonglong2(0ull, 0ull);
        smt[ml][bcc]     = v.x;
        smt[ml][bcc + 1] = v.y;
    }
    __syncthreads();

    const int bcr = t >> 4;            // 0..15
    const int mc  = (t & 15) * 2;      // 0..30
#pragma unroll
    for (int r = 0; r < 4; ++r) {
        int bcl = bcr + r * 16;
        ulonglong2 v;
        v.x = smt[mc][bcl];
        v.y = smt[mc + 1][bcl];
        *(ulonglong2*)(out + (((size_t)(bc0 + bcl)) * MDIM + l) * MDIM + m0 + mc) = v;
    }
}

// ---------------------------------------------------------------------------

extern "C" void kernel_launch(void* const* d_in, const int* in_sizes, int n_in,
                              void* d_out, int out_size)
{
    (void)in_sizes; (void)n_in; (void)out_size;
    const float* x      = (const float*)d_in[0];
    const float* weight = (const float*)d_in[1];
    const float* cosb   = (const float*)d_in[2];
    const float* sinb   = (const float*)d_in[3];

    dim3 gA(16, 96, 3);
    sht_stageA<<<gA, 256>>>(x, cosb, sinb);

    dim3 gB(16, 3, 192);
    sht_stageB<<<gB, 128>>>(weight);

    dim3 gT(16, 6, 192);
    sht_transpose<<<gT, 256>>>((u64*)d_out);
}

// round 11
// speedup vs baseline: 1.8107x; 1.2785x over previous
#include <cuda_runtime.h>

#define NGRID   41088
#define PMAX    404
#define MDIM    192
#define KR      192
#define KF      96
#define BCN     1024
#define TWO_PI_F 6.28318530717958647692f

typedef unsigned long long u64;
typedef unsigned int u32;

// Pre-folded stage-A output: (re,im) pairs, layout [m][kf][bc], kf in [0,96)
__device__ u64 g_rip[(size_t)MDIM * KF * BCN];   // A+ = A[k] + A[191-k]
__device__ u64 g_rim[(size_t)MDIM * KF * BCN];   // A- = A[k] - A[191-k]
// Stage-B staging: (re,im) pairs, layout [m][l][bc]
__device__ u64 g_st[(size_t)MDIM * MDIM * BCN];

__device__ __forceinline__ u64 ffma2(u64 a, u64 b, u64 c) {
    u64 d; asm("fma.rn.f32x2 %0,%1,%2,%3;" : "=l"(d) : "l"(a), "l"(b), "l"(c)); return d;
}
__device__ __forceinline__ u64 fmul2(u64 a, u64 b) {
    u64 d; asm("mul.rn.f32x2 %0,%1,%2;" : "=l"(d) : "l"(a), "l"(b)); return d;
}
__device__ __forceinline__ u64 fadd2(u64 a, u64 b) {
    u64 d; asm("add.rn.f32x2 %0,%1,%2;" : "=l"(d) : "l"(a), "l"(b)); return d;
}
__device__ __forceinline__ u64 pk2(float lo, float hi) {
    u64 r; asm("mov.b64 %0,{%1,%2};" : "=l"(r) : "f"(lo), "f"(hi)); return r;
}
__device__ __forceinline__ void lds2(u64& a, u64& b, u32 addr) {
    asm volatile("ld.shared.v2.u64 {%0,%1},[%2];" : "=l"(a), "=l"(b) : "r"(addr));
}
__device__ __forceinline__ float4 lds4f(u32 addr) {
    float4 v;
    asm volatile("ld.shared.v4.f32 {%0,%1,%2,%3},[%4];"
                 : "=f"(v.x), "=f"(v.y), "=f"(v.z), "=f"(v.w) : "r"(addr));
    return v;
}
__device__ __forceinline__ void sts4(u32 addr, float a, float b, float c, float d) {
    asm volatile("st.shared.v4.f32 [%0],{%1,%2,%3,%4};" :: "r"(addr), "f"(a), "f"(b), "f"(c), "f"(d));
}
__device__ __forceinline__ void sts2(u32 addr, float a, float b) {
    asm volatile("st.shared.v2.f32 [%0],{%1,%2};" :: "r"(addr), "f"(a), "f"(b));
}
__device__ __forceinline__ void sts1(u32 addr, float a) {
    asm volatile("st.shared.f32 [%0],%1;" :: "r"(addr), "f"(a));
}
__device__ __forceinline__ u32 s2u(const void* p) {
    u32 a; asm("{.reg .u64 t; cvta.to.shared.u64 t,%1; cvt.u32.u64 %0,t;}" : "=r"(a) : "l"(p)); return a;
}
__device__ __forceinline__ void cpa16(u32 dst, const void* src, int bytes) {
    asm volatile("cp.async.cg.shared.global [%0],[%1],16,%2;" :: "r"(dst), "l"(src), "r"(bytes));
}
__device__ __forceinline__ void cpcommit() { asm volatile("cp.async.commit_group;"); }
__device__ __forceinline__ void cpwait0()  { asm volatile("cp.async.wait_group 0;"); }

// ---------------------------------------------------------------------------
// Stage A: folded per-ring DFT on ring PAIRS (k1, 191-k1).
// LONS is pole-symmetric: nlon, basis identical for both rings of a pair.
//   re[m,bc] = sum_{q=0..nlon/2} c[q,m]*xplus[bc,q]   (per ring)
// Epilogue emits pre-folded A+ = A(k1)+A(k2), A- = A(k1)-A(k2), scaled 2*pi.
// grid = (16 bc-tiles of 64, 96 pairs big-first, 3 m-tiles of 64), 256 thr.
// Thread tile: 4 m x (4 bc ring0 + 4 bc ring1); bc pairs {2tb,2tb+1,+32} so
// every x-lds2 is a conflict-free 256B-span load (the r10 regression was a
// 4-way bank conflict from tb*32 addressing).
// ---------------------------------------------------------------------------
extern "C" __global__ void __launch_bounds__(256, 2)
sht_stageA(const float* __restrict__ x,
           const float* __restrict__ cosb,
           const float* __restrict__ sinb)
{
    __shared__ __align__(16) unsigned char sm[2 * 16 * 512 + 2 * 16 * 1024]; // 49152
    const int t   = threadIdx.x;
    const int bc0 = blockIdx.x * 64;
    const int k1  = 95 - blockIdx.y;        // big rings first (k1=95: nlon 404)
    const int m0  = blockIdx.z * 64;

    const int nlon  = 24 + 4 * k1;
    const int slon1 = 2 * k1 * k1 + 22 * k1;
    const int q2    = k1 + 1;               // = 192 - k2, k2 = 96 + blockIdx.y
    const int slon2 = NGRID - (2 * q2 * q2 + 22 * q2);
    int mmax = 12 + 2 * k1;
    if (mmax > MDIM - 1) mmax = MDIM - 1;   // identical for both rings of pair
    if (m0 > mmax) return;                  // inactive m-tile: never read downstream
    const int half   = nlon >> 1;
    const int ntiles = (half + 16) >> 4;    // ceil((half+1)/16)

    const u32 sb = s2u(sm);
    const u32 CS = sb;                      // [buf][16q][64 m u64], row 512 B
    const u32 XS = sb + 16384;              // [buf][16q][2 ring][64 bc u64], row 1024 B

    // staging roles
    const int ppb = t >> 4, mq = (t & 15) * 4;   // basis: 1 q-row, 4 m
    const int bcr = t >> 1, pq = (t & 1) * 8;    // x: 1 (ring,bc)-row, 8 q
    const int ring = bcr >> 6, bcl = bcr & 63;

    // compute roles
    const int tm = t >> 4, tb = t & 15;          // 4 m, 4 bc per ring

    const float* xrow  = x + (size_t)(bc0 + bcl) * NGRID + (ring ? slon2 : slon1);
    const float* cbase = cosb + ((size_t)k1 * PMAX) * MDIM + m0 + mq;
    const float* sbase = sinb + ((size_t)k1 * PMAX) * MDIM + m0 + mq;

    u64 acc0[4][4], acc1[4][4];
#pragma unroll
    for (int j = 0; j < 4; j++)
#pragma unroll
        for (int i = 0; i < 4; i++) { acc0[j][i] = 0ull; acc1[j][i] = 0ull; }

    float4 c4, s4, fw0, fw1, bw0, bw1;
    float ps0, ps1;
    int p0s;
    const float4 z4 = make_float4(0.f, 0.f, 0.f, 0.f);

    auto prefetch = [&](int p0) {
        p0s = p0;
        int p = p0 + ppb;                   // p <= 207 < PMAX: in-bounds
        c4 = *(const float4*)(cbase + (size_t)p * MDIM);
        s4 = *(const float4*)(sbase + (size_t)p * MDIM);
        int q0 = p0 + pq;
        if (q0 <= half) {
            fw0 = *(const float4*)(xrow + q0);
            bw0 = *(const float4*)(xrow + nlon - q0 - 4);
            ps0 = (q0 >= 1) ? xrow[nlon - q0] : 0.f;
        } else { fw0 = z4; bw0 = z4; ps0 = 0.f; }
        int q1 = q0 + 4;
        if (q1 <= half) {
            fw1 = *(const float4*)(xrow + q1);
            bw1 = *(const float4*)(xrow + nlon - q1 - 4);
            ps1 = xrow[nlon - q1];
        } else { fw1 = z4; bw1 = z4; ps1 = 0.f; }
    };

    auto fold_emit = [&](u32 a, float4 f, float4 b, float ps, int qv) {
        float fr[4] = {f.x, f.y, f.z, f.w};
        float pr[4] = {ps, b.w, b.z, b.y};
#pragma unroll
        for (int i = 0; i < 4; i++) {
            int q = qv + i;
            bool valid = q <= half;
            bool spec  = (q == 0) || (q == half);
            float pl = valid ? (spec ? fr[i] : fr[i] + pr[i]) : 0.f;
            float mi = (valid && !spec) ? fr[i] - pr[i] : 0.f;
            sts2(a + i * 1024, pl, mi);
        }
    };

    auto store_tile = [&](int buf) {
        u32 cs = CS + buf * 8192 + ppb * 512 + mq * 8;
        sts4(cs,      c4.x, s4.x, c4.y, s4.y);
        sts4(cs + 16, c4.z, s4.z, c4.w, s4.w);
        u32 xa = XS + buf * 16384 + pq * 1024 + ring * 512 + bcl * 8;
        int q0 = p0s + pq;
        fold_emit(xa,        fw0, bw0, ps0, q0);
        fold_emit(xa + 4096, fw1, bw1, ps1, q0 + 4);
    };

    auto compute = [&](int buf) {
        u32 cs = CS + buf * 8192 + tm * 32;
        u32 xs = XS + buf * 16384 + tb * 16;
#pragma unroll
        for (int pp = 0; pp < 16; ++pp) {
            u64 b0, b1, b2, b3;
            lds2(b0, b1, cs + pp * 512);
            lds2(b2, b3, cs + pp * 512 + 16);
            u64 v[4], u[4];
            lds2(v[0], v[1], xs + pp * 1024);          // ring0 bc {2tb, 2tb+1}
            lds2(v[2], v[3], xs + pp * 1024 + 256);    // ring0 bc {2tb+32, 2tb+33}
            lds2(u[0], u[1], xs + pp * 1024 + 512);    // ring1 bc {2tb, 2tb+1}
            lds2(u[2], u[3], xs + pp * 1024 + 768);    // ring1 bc {2tb+32, 2tb+33}
#pragma unroll
            for (int i = 0; i < 4; i++) {
                acc0[0][i] = ffma2(b0, v[i], acc0[0][i]);
                acc0[1][i] = ffma2(b1, v[i], acc0[1][i]);
                acc0[2][i] = ffma2(b2, v[i], acc0[2][i]);
                acc0[3][i] = ffma2(b3, v[i], acc0[3][i]);
                acc1[0][i] = ffma2(b0, u[i], acc1[0][i]);
                acc1[1][i] = ffma2(b1, u[i], acc1[1][i]);
                acc1[2][i] = ffma2(b2, u[i], acc1[2][i]);
                acc1[3][i] = ffma2(b3, u[i], acc1[3][i]);
            }
        }
    };

    prefetch(0);
    store_tile(0);
    __syncthreads();
    for (int ti = 0; ti < ntiles; ++ti) {
        bool nx = (ti + 1) < ntiles;
        if (nx) prefetch((ti + 1) << 4);
        compute(ti & 1);
        if (nx) store_tile((ti + 1) & 1);
        __syncthreads();
    }

    // epilogue: fold across hemisphere pair, scale by 2*pi, STG.128
    // thread bc = {2tb, 2tb+1} (acc[.][0..1]) and {2tb+32, 2tb+33} (acc[.][2..3])
    const u64 tp2  = pk2(TWO_PI_F, TWO_PI_F);
    const u64 NEG1 = pk2(-1.f, -1.f);
#pragma unroll
    for (int j = 0; j < 4; j++) {
        size_t base = ((size_t)(m0 + tm * 4 + j) * KF + k1) * BCN + bc0 + tb * 2;
        u64* op = g_rip + base;
        u64* om = g_rim + base;
        ulonglong2 wp0, wp1, wm0, wm1;
        wp0.x = fmul2(fadd2(acc0[j][0], acc1[j][0]), tp2);
        wp0.y = fmul2(fadd2(acc0[j][1], acc1[j][1]), tp2);
        wp1.x = fmul2(fadd2(acc0[j][2], acc1[j][2]), tp2);
        wp1.y = fmul2(fadd2(acc0[j][3], acc1[j][3]), tp2);
        wm0.x = fmul2(ffma2(acc1[j][0], NEG1, acc0[j][0]), tp2);
        wm0.y = fmul2(ffma2(acc1[j][1], NEG1, acc0[j][1]), tp2);
        wm1.x = fmul2(ffma2(acc1[j][2], NEG1, acc0[j][2]), tp2);
        wm1.y = fmul2(ffma2(acc1[j][3], NEG1, acc0[j][3]), tp2);
        *(ulonglong2*)op        = wp0;
        *(ulonglong2*)(op + 32) = wp1;
        *(ulonglong2*)om        = wm0;
        *(ulonglong2*)(om + 32) = wm1;
    }
}

// ---------------------------------------------------------------------------
// Stage B: per-m GEMM on pre-folded operands, parity-coherent warps.
//   weight[m,l,k] = (-1)^(l+m) weight[m,l,191-k]
//   st[m,l,bc] = sum_{k in [klo,95]} W[m,l,k] * ( (l+m) even ? A+[k] : A-[k] )
// grid = (16 bc-tiles of 64, 3 l-tiles of 64, 192 m), block = 128.
// ---------------------------------------------------------------------------
extern "C" __global__ void __launch_bounds__(128, 4)
sht_stageB(const float* __restrict__ weight)
{
    __shared__ __align__(16) unsigned char sm[4 * 16 * 512 + 2 * 16 * 256];  // 40960
    const int t   = threadIdx.x;
    const int bc0 = blockIdx.x * 64;
    const int l0  = blockIdx.y * 64;
    const int m   = blockIdx.z;
    if (l0 + 63 < m) return;                // zero triangle: handled by transpose

    const int klo = (m <= 12) ? 0 : ((m - 11) >> 1);   // klo <= 90 < 96
    const int kb0 = klo & ~15;
    const int nkt = ((95 - kb0) >> 4) + 1;  // tiles cover [kb0, 95] exactly

    const u32 sb  = s2u(sm);
    const u32 APS = sb;                     // A+ : [buf][16k][64bc u64], row 512 B
    const u32 AMS = sb + 16384;             // A-
    const u32 WS  = sb + 32768;             // W  : [buf][16k][2 par][32 lc] f32, row 256 B

    // staging roles
    const int lr = t >> 1, kq = (t & 1) * 8;       // W: 1 l-row, 8 k
    const int wpar = (lr + m) & 1, wlc = lr >> 1;

    // compute roles
    const int w = t >> 5, lane = t & 31;
    const int pw  = w & 1;                  // warp parity: 0 -> A+, 1 -> A-
    const int h   = w >> 1;                 // bc half
    const int lc0 = (lane >> 3) * 8;        // 8 consecutive compacted l
    const int bto = h * 32 + (lane & 7) * 4;
    const int dlt = pw ^ (m & 1);           // actual l = l0 + 2*lc + dlt

    const float* wrow   = weight + ((size_t)m * MDIM + l0 + lr) * KR;
    const u64*   apbase = g_rip + ((size_t)m * KF) * BCN + bc0;
    const u64*   ambase = g_rim + ((size_t)m * KF) * BCN + bc0;

    u64 acc[8][4];
#pragma unroll
    for (int j = 0; j < 8; j++)
#pragma unroll
        for (int i = 0; i < 4; i++) acc[j][i] = 0ull;

    float4 w40, w41;
    auto cpa_tile = [&](int buf, int kb) {
#pragma unroll
        for (int c = 0; c < 4; c++) {
            int chunk = t * 4 + c;          // 0..511
            int kk = chunk >> 5, col = chunk & 31;
            int kg = kb + kk;               // kg <= 95 always
            int bytes = (kg >= klo) ? 16 : 0;   // zero-fill below band
            cpa16(APS + buf * 8192 + kk * 512 + col * 16,
                  apbase + (size_t)kg * BCN + col * 2, bytes);
            cpa16(AMS + buf * 8192 + kk * 512 + col * 16,
                  ambase + (size_t)kg * BCN + col * 2, bytes);
        }
        cpcommit();
    };
    auto ldW = [&](int kb) {
        w40 = *(const float4*)(wrow + kb + kq);
        w41 = *(const float4*)(wrow + kb + kq + 4);
    };
    auto stW = [&](int buf) {
        u32 ws = WS + buf * 4096 + wpar * 128 + wlc * 4;
        sts1(ws + (kq + 0) * 256, w40.x);
        sts1(ws + (kq + 1) * 256, w40.y);
        sts1(ws + (kq + 2) * 256, w40.z);
        sts1(ws + (kq + 3) * 256, w40.w);
        sts1(ws + (kq + 4) * 256, w41.x);
        sts1(ws + (kq + 5) * 256, w41.y);
        sts1(ws + (kq + 6) * 256, w41.z);
        sts1(ws + (kq + 7) * 256, w41.w);
    };

    const u32 AT = pw ? AMS : APS;

    auto compute = [&](int buf) {
        u32 as_ = AT + buf * 8192 + bto * 8;
        u32 ws  = WS + buf * 4096 + pw * 128 + lc0 * 4;
#pragma unroll
        for (int kk = 0; kk < 16; ++kk) {
            u64 a[4];
            lds2(a[0], a[1], as_ + kk * 512);
            lds2(a[2], a[3], as_ + kk * 512 + 16);
            float4 f0 = lds4f(ws + kk * 256);
            float4 f1 = lds4f(ws + kk * 256 + 16);
            const float fw[8] = {f0.x, f0.y, f0.z, f0.w, f1.x, f1.y, f1.z, f1.w};
#pragma unroll
            for (int j = 0; j < 8; j++) {
                u64 ww = pk2(fw[j], fw[j]);
#pragma unroll
                for (int i = 0; i < 4; i++)
                    acc[j][i] = ffma2(a[i], ww, acc[j][i]);
            }
        }
    };

    cpa_tile(0, kb0);
    ldW(kb0);
    stW(0);
    cpwait0();
    __syncthreads();
    for (int ti = 0; ti < nkt; ++ti) {
        int kb = kb0 + ((ti + 1) << 4);
        bool nx = (ti + 1) < nkt;
        if (nx) { cpa_tile((ti + 1) & 1, kb); ldW(kb); }
        compute(ti & 1);
        if (nx) { stW((ti + 1) & 1); cpwait0(); }
        __syncthreads();
    }

    // coalesced staging writes: [m][l][bc]; rows l = l0 + 2*(lc0+j) + dlt
#pragma unroll
    for (int j = 0; j < 8; j++) {
        int l = l0 + 2 * (lc0 + j) + dlt;
        u64* o = g_st + (((size_t)m * MDIM) + l) * BCN + bc0 + bto;
        ulonglong2 w0, w1;
        w0.x = acc[j][0]; w0.y = acc[j][1];
        w1.x = acc[j][2]; w1.y = acc[j][3];
        *(ulonglong2*)o       = w0;
        *(ulonglong2*)(o + 2) = w1;
    }
}

// ---------------------------------------------------------------------------
// Transpose: out[bc][l][m] <- g_st[m][l][bc]; zero for l < m.
// grid = (16 bc-tiles of 64, 6 m-tiles of 32, 192 l), block = 256.
// ---------------------------------------------------------------------------
extern "C" __global__ void __launch_bounds__(256)
sht_transpose(u64* __restrict__ out)
{
    __shared__ u64 smt[32][65];
    const int t   = threadIdx.x;
    const int bc0 = blockIdx.x * 64;
    const int m0  = blockIdx.y * 32;
    const int l   = blockIdx.z;

    const int mr  = t >> 5;            // 0..7
    const int bcc = (t & 31) * 2;      // 0..62
#pragma unroll
    for (int r = 0; r < 4; ++r) {
        int ml = mr + r * 8;
        ulonglong2 v;
        if (l >= m0 + ml)
            v = *(const ulonglong2*)(g_st + (((size_t)(m0 + ml)) * MDIM + l) * BCN + bc0 + bcc);
        else
            v = make_ulonglong2(0ull, 0ull);
        smt[ml][bcc]     = v.x;
        smt[ml][bcc + 1] = v.y;
    }
    __syncthreads();

    const int bcr = t >> 4;            // 0..15
    const int mc  = (t & 15) * 2;      // 0..30
#pragma unroll
    for (int r = 0; r < 4; ++r) {
        int bcl = bcr + r * 16;
        ulonglong2 v;
        v.x = smt[mc][bcl];
        v.y = smt[mc + 1][bcl];
        *(ulonglong2*)(out + (((size_t)(bc0 + bcl)) * MDIM + l) * MDIM + m0 + mc) = v;
    }
}

// ---------------------------------------------------------------------------

extern "C" void kernel_launch(void* const* d_in, const int* in_sizes, int n_in,
                              void* d_out, int out_size)
{
    (void)in_sizes; (void)n_in; (void)out_size;
    const float* x      = (const float*)d_in[0];
    const float* weight = (const float*)d_in[1];
    const float* cosb   = (const float*)d_in[2];
    const float* sinb   = (const float*)d_in[3];

    dim3 gA(16, 96, 3);
    sht_stageA<<<gA, 256>>>(x, cosb, sinb);

    dim3 gB(16, 3, 192);
    sht_stageB<<<gB, 128>>>(weight);

    dim3 gT(16, 6, 192);
    sht_transpose<<<gT, 256>>>((u64*)d_out);
}